// round 1
// baseline (speedup 1.0000x reference)
#include <cuda_runtime.h>
#include <math.h>

// Problem shape (fixed by reference): B=8, T=2048, D=1024
#define BB   8
#define TT   2048
#define DD   1024
#define MM   (BB*TT)          // 16384 rows
#define NCHUNK 32
#define CHLEN  64             // 32*64 = 2048

// ---------------- scratch (static device globals: allocation-guard safe) ----
__device__ float g_zlin[(size_t)MM * DD];   // zlin, later reused for y (swish output)
__device__ float g_a[(size_t)MM * DD];      // a_t = 1 - z_t
__device__ float g_b[(size_t)MM * DD];      // b_t = z_t * h_tilde_t
__device__ float g_Ac[BB * NCHUNK * DD];    // per-chunk prefix A
__device__ float g_Bc[BB * NCHUNK * DD];    // per-chunk prefix B
__device__ float g_hinit[BB * NCHUNK * DD]; // per-chunk initial h

__device__ __forceinline__ float sigmoidf_fast(float v) {
    return 1.0f / (1.0f + __expf(-v));
}

// ---------------- SGEMM 128x128x8, 256 threads, 8x8 per thread ----------------
// C[m,n] = sum_k A[m,k] * W[k,n];  A: [MM,DD] row-major, W: [DD,DD] row-major.
// EPI=false: store raw accumulator into g_zlin.
// EPI=true : hlin = acc + bh[n]; z = sigmoid(g_zlin + bz[n]);
//            g_a = 1-z; g_b = z*hlin.
template <bool EPI>
__global__ __launch_bounds__(256)
void sgemm_kernel(const float* __restrict__ A, const float* __restrict__ W,
                  const float* __restrict__ bz, const float* __restrict__ bh)
{
    const int BM = 128, BN = 128, BK = 8, TM = 8, TN = 8;
    __shared__ float As[BK * BM];
    __shared__ float Bs[BK * BN];

    const int tid  = threadIdx.x;
    const int cRow = blockIdx.y;           // M tile
    const int cCol = blockIdx.x;           // N tile

    const float* Aptr = A + (size_t)cRow * BM * DD;
    const float* Wptr = W + cCol * BN;

    const int innerRowA = tid >> 1;        // 128 rows, 2 float4 per row
    const int innerColA = tid & 1;
    const int innerRowB = tid >> 5;        // 8 rows, 32 float4 per row
    const int innerColB = tid & 31;

    const int threadRow = tid >> 4;        // 16
    const int threadCol = tid & 15;        // 16

    float acc[TM * TN];
#pragma unroll
    for (int i = 0; i < TM * TN; i++) acc[i] = 0.0f;
    float regA[TM], regB[TN];

    for (int k0 = 0; k0 < DD; k0 += BK) {
        float4 av = *(const float4*)(Aptr + innerRowA * DD + k0 + innerColA * 4);
        As[(innerColA * 4 + 0) * BM + innerRowA] = av.x;
        As[(innerColA * 4 + 1) * BM + innerRowA] = av.y;
        As[(innerColA * 4 + 2) * BM + innerRowA] = av.z;
        As[(innerColA * 4 + 3) * BM + innerRowA] = av.w;

        float4 bv = *(const float4*)(Wptr + (size_t)(k0 + innerRowB) * DD + innerColB * 4);
        *(float4*)(&Bs[innerRowB * BN + innerColB * 4]) = bv;

        __syncthreads();

#pragma unroll
        for (int k = 0; k < BK; k++) {
#pragma unroll
            for (int i = 0; i < TM; i++) regA[i] = As[k * BM + threadRow * TM + i];
#pragma unroll
            for (int j = 0; j < TN; j++) regB[j] = Bs[k * BN + threadCol * TN + j];
#pragma unroll
            for (int i = 0; i < TM; i++)
#pragma unroll
                for (int j = 0; j < TN; j++)
                    acc[i * TN + j] = fmaf(regA[i], regB[j], acc[i * TN + j]);
        }
        __syncthreads();
    }

    const int rowBase = cRow * BM + threadRow * TM;
    const int colBase = cCol * BN + threadCol * TN;

#pragma unroll
    for (int i = 0; i < TM; i++) {
        const size_t rb = (size_t)(rowBase + i) * DD + colBase;
        if (!EPI) {
#pragma unroll
            for (int j4 = 0; j4 < TN / 4; j4++) {
                float4 v;
                v.x = acc[i * TN + j4 * 4 + 0];
                v.y = acc[i * TN + j4 * 4 + 1];
                v.z = acc[i * TN + j4 * 4 + 2];
                v.w = acc[i * TN + j4 * 4 + 3];
                *(float4*)(&g_zlin[rb + j4 * 4]) = v;
            }
        } else {
#pragma unroll
            for (int j4 = 0; j4 < TN / 4; j4++) {
                float4 zl = *(const float4*)(&g_zlin[rb + j4 * 4]);
                float4 bzv = *(const float4*)(&bz[colBase + j4 * 4]);
                float4 bhv = *(const float4*)(&bh[colBase + j4 * 4]);
                float4 av, bbv;
                {
                    float z = sigmoidf_fast(zl.x + bzv.x);
                    float hl = acc[i * TN + j4 * 4 + 0] + bhv.x;
                    av.x = 1.0f - z; bbv.x = z * hl;
                }
                {
                    float z = sigmoidf_fast(zl.y + bzv.y);
                    float hl = acc[i * TN + j4 * 4 + 1] + bhv.y;
                    av.y = 1.0f - z; bbv.y = z * hl;
                }
                {
                    float z = sigmoidf_fast(zl.z + bzv.z);
                    float hl = acc[i * TN + j4 * 4 + 2] + bhv.z;
                    av.z = 1.0f - z; bbv.z = z * hl;
                }
                {
                    float z = sigmoidf_fast(zl.w + bzv.w);
                    float hl = acc[i * TN + j4 * 4 + 3] + bhv.w;
                    av.w = 1.0f - z; bbv.w = z * hl;
                }
                *(float4*)(&g_a[rb + j4 * 4]) = av;
                *(float4*)(&g_b[rb + j4 * 4]) = bbv;
            }
        }
    }
}

// ---------------- scan pass 1: per-chunk (A, B) prefix ----------------
// thread g handles (b, chunk, d): g = (b*NCHUNK + chunk)*DD + d
__global__ __launch_bounds__(256)
void scan_pass1()
{
    const int g  = blockIdx.x * blockDim.x + threadIdx.x;
    const int d  = g & (DD - 1);
    const int bc = g >> 10;                    // b*NCHUNK + chunk
    const size_t base = ((size_t)bc * CHLEN) * DD + d;

    float Ar = 1.0f, Br = 0.0f;
#pragma unroll 8
    for (int t = 0; t < CHLEN; t++) {
        const float a  = g_a[base + (size_t)t * DD];
        const float bb = g_b[base + (size_t)t * DD];
        Br = fmaf(a, Br, bb);
        Ar *= a;
    }
    g_Ac[g] = Ar;
    g_Bc[g] = Br;
}

// ---------------- scan pass 2: sequential scan over the 32 chunk summaries --
__global__ __launch_bounds__(256)
void scan_pass2()
{
    const int g = blockIdx.x * blockDim.x + threadIdx.x;   // 8192 threads
    const int d = g & (DD - 1);
    const int b = g >> 10;
    float h = 0.0f;
#pragma unroll
    for (int c = 0; c < NCHUNK; c++) {
        const int idx = (b * NCHUNK + c) * DD + d;
        g_hinit[idx] = h;
        h = fmaf(g_Ac[idx], h, g_Bc[idx]);
    }
}

// ---------------- scan pass 3: final scan + swish, write y into g_zlin ------
__global__ __launch_bounds__(256)
void scan_pass3(const float* __restrict__ swish_beta)
{
    const int g  = blockIdx.x * blockDim.x + threadIdx.x;
    const int d  = g & (DD - 1);
    const int bc = g >> 10;
    const size_t base = ((size_t)bc * CHLEN) * DD + d;
    const float beta = __ldg(swish_beta);

    float h = g_hinit[g];
#pragma unroll 8
    for (int t = 0; t < CHLEN; t++) {
        const size_t idx = base + (size_t)t * DD;
        h = fmaf(g_a[idx], h, g_b[idx]);
        const float s = beta * h;
        g_zlin[idx] = s * sigmoidf_fast(s);   // swish
    }
}

// ---------------- LayerNorm over D, one block per row ----------------
__global__ __launch_bounds__(256)
void ln_kernel(float* __restrict__ out,
               const float* __restrict__ gamma,
               const float* __restrict__ lbeta)
{
    const int row = blockIdx.x;
    const int tid = threadIdx.x;
    const float4 v = ((const float4*)(g_zlin + (size_t)row * DD))[tid];

    float s  = v.x + v.y + v.z + v.w;
    float sq = v.x * v.x + v.y * v.y + v.z * v.z + v.w * v.w;

    // block reduce (sum, sumsq)
#pragma unroll
    for (int o = 16; o > 0; o >>= 1) {
        s  += __shfl_xor_sync(0xffffffffu, s, o);
        sq += __shfl_xor_sync(0xffffffffu, sq, o);
    }
    __shared__ float sa[8], sb[8];
    const int w = tid >> 5, l = tid & 31;
    if (l == 0) { sa[w] = s; sb[w] = sq; }
    __syncthreads();
    if (w == 0) {
        s  = (l < 8) ? sa[l] : 0.0f;
        sq = (l < 8) ? sb[l] : 0.0f;
#pragma unroll
        for (int o = 4; o > 0; o >>= 1) {
            s  += __shfl_xor_sync(0xffffffffu, s, o);
            sq += __shfl_xor_sync(0xffffffffu, sq, o);
        }
        if (l == 0) { sa[0] = s; sb[0] = sq; }
    }
    __syncthreads();
    const float mu  = sa[0] * (1.0f / DD);
    const float var = sb[0] * (1.0f / DD) - mu * mu;
    const float inv = rsqrtf(var + 1e-5f);

    const float4 gm = ((const float4*)gamma)[tid];
    const float4 bt = ((const float4*)lbeta)[tid];
    float4 o;
    o.x = (v.x - mu) * inv * gm.x + bt.x;
    o.y = (v.y - mu) * inv * gm.y + bt.y;
    o.z = (v.z - mu) * inv * gm.z + bt.z;
    o.w = (v.w - mu) * inv * gm.w + bt.w;
    ((float4*)(out + (size_t)row * DD))[tid] = o;
}

// ---------------- launch ----------------
extern "C" void kernel_launch(void* const* d_in, const int* in_sizes, int n_in,
                              void* d_out, int out_size)
{
    const float* x     = (const float*)d_in[0];
    const float* Wz    = (const float*)d_in[1];
    const float* bz    = (const float*)d_in[2];
    const float* Wh    = (const float*)d_in[3];
    const float* bh    = (const float*)d_in[4];
    const float* sbeta = (const float*)d_in[5];
    const float* gamma = (const float*)d_in[6];
    const float* lbeta = (const float*)d_in[7];
    float* out = (float*)d_out;

    dim3 gemmGrid(DD / 128, MM / 128);   // (8, 128)
    dim3 blk(256);

    sgemm_kernel<false><<<gemmGrid, blk>>>(x, Wz, nullptr, nullptr);
    sgemm_kernel<true ><<<gemmGrid, blk>>>(x, Wh, bz, bh);

    scan_pass1<<<(BB * NCHUNK * DD) / 256, 256>>>();
    scan_pass2<<<(BB * DD) / 256, 256>>>();
    scan_pass3<<<(BB * NCHUNK * DD) / 256, 256>>>(sbeta);

    ln_kernel<<<MM, 256>>>(out, gamma, lbeta);
}

// round 3
// speedup vs baseline: 2.5310x; 2.5310x over previous
#include <cuda_runtime.h>
#include <cuda_bf16.h>
#include <math.h>
#include <stdint.h>

// Problem shape (fixed): B=8, T=2048, D=1024
#define BB   8
#define TT   2048
#define DD   1024
#define MM   (BB*TT)          // 16384 rows
#define NCHUNK 32
#define CHLEN  64

// GEMM tiling: CTA 128x128, warp 64x32, BK=32 bf16 (64B rows), 3-term split K=3072
#define BKE    32             // K elements per chunk
#define NCH    96             // 3 segs * 32 chunks
#define NST    3
#define A_HALF 8192           // 128 rows * 64B
#define STAGE_B 16384
#define SMEM_GEMM (NST * STAGE_B)   // 49152 = 48KB (fits default dynamic limit)

// ---------------- scratch (device globals) ----------------
__device__ float g_zlin[(size_t)MM * DD];
__device__ float g_a[(size_t)MM * DD];
__device__ float g_b[(size_t)MM * DD];
__device__ float g_Ac[BB * NCHUNK * DD];
__device__ float g_Bc[BB * NCHUNK * DD];
__device__ float g_hinit[BB * NCHUNK * DD];

__device__ __nv_bfloat16 g_ahi[(size_t)MM * DD];
__device__ __nv_bfloat16 g_alo[(size_t)MM * DD];
__device__ __nv_bfloat16 g_Wtz_hi[DD * DD];
__device__ __nv_bfloat16 g_Wtz_lo[DD * DD];
__device__ __nv_bfloat16 g_Wth_hi[DD * DD];
__device__ __nv_bfloat16 g_Wth_lo[DD * DD];

__device__ __forceinline__ float sigmoidf_fast(float v) {
    return 1.0f / (1.0f + __expf(-v));
}

// ---------------- PTX helpers ----------------
__device__ __forceinline__ uint32_t smem_u32(const void* p) {
    uint32_t a;
    asm("{ .reg .u64 t; cvta.to.shared.u64 t, %1; cvt.u32.u64 %0, t; }" : "=r"(a) : "l"(p));
    return a;
}
#define SWZ64(o) ((o) ^ (((o) >> 3) & 0x30))

__device__ __forceinline__ void cp16(uint32_t s, const void* g) {
    asm volatile("cp.async.cg.shared.global [%0], [%1], 16;" :: "r"(s), "l"(g));
}
__device__ __forceinline__ void cp_commit() {
    asm volatile("cp.async.commit_group;" ::: "memory");
}
__device__ __forceinline__ void ldsm_x4(uint32_t& r0, uint32_t& r1, uint32_t& r2,
                                        uint32_t& r3, uint32_t addr) {
    asm volatile("ldmatrix.sync.aligned.m8n8.x4.shared.b16 {%0,%1,%2,%3}, [%4];"
                 : "=r"(r0), "=r"(r1), "=r"(r2), "=r"(r3) : "r"(addr));
}
__device__ __forceinline__ void mma_bf16(float* d, const uint32_t* a, const uint32_t* b) {
    asm volatile(
        "mma.sync.aligned.m16n8k16.row.col.f32.bf16.bf16.f32 "
        "{%0,%1,%2,%3},{%4,%5,%6,%7},{%8,%9},{%0,%1,%2,%3};"
        : "+f"(d[0]), "+f"(d[1]), "+f"(d[2]), "+f"(d[3])
        : "r"(a[0]), "r"(a[1]), "r"(a[2]), "r"(a[3]), "r"(b[0]), "r"(b[1]));
}

// ---------------- prep: split x into hi/lo bf16 ----------------
__global__ __launch_bounds__(256)
void split_x_kernel(const float* __restrict__ x)
{
    const size_t i4 = (size_t)blockIdx.x * 256 + threadIdx.x;
    const float4 v = ((const float4*)x)[i4];
    __nv_bfloat16 h0 = __float2bfloat16(v.x);
    __nv_bfloat16 h1 = __float2bfloat16(v.y);
    __nv_bfloat16 h2 = __float2bfloat16(v.z);
    __nv_bfloat16 h3 = __float2bfloat16(v.w);
    __nv_bfloat162 hi0, hi1, lo0, lo1;
    hi0.x = h0; hi0.y = h1; hi1.x = h2; hi1.y = h3;
    lo0.x = __float2bfloat16(v.x - __bfloat162float(h0));
    lo0.y = __float2bfloat16(v.y - __bfloat162float(h1));
    lo1.x = __float2bfloat16(v.z - __bfloat162float(h2));
    lo1.y = __float2bfloat16(v.w - __bfloat162float(h3));
    ((__nv_bfloat162*)g_ahi)[i4 * 2]     = hi0;
    ((__nv_bfloat162*)g_ahi)[i4 * 2 + 1] = hi1;
    ((__nv_bfloat162*)g_alo)[i4 * 2]     = lo0;
    ((__nv_bfloat162*)g_alo)[i4 * 2 + 1] = lo1;
}

// ---------------- prep: transpose + split W -> Wt[n][k] hi/lo ----------------
__global__ __launch_bounds__(256)
void transpose_split_kernel(const float* __restrict__ Wz, const float* __restrict__ Wh)
{
    __shared__ float sm[32][33];
    const float* W = (blockIdx.z == 0) ? Wz : Wh;
    __nv_bfloat16* Whi = (blockIdx.z == 0) ? g_Wtz_hi : g_Wth_hi;
    __nv_bfloat16* Wlo = (blockIdx.z == 0) ? g_Wtz_lo : g_Wth_lo;

    const int k0 = blockIdx.y * 32;
    const int n0 = blockIdx.x * 32;
    const int r = threadIdx.x >> 5;
    const int c = threadIdx.x & 31;
#pragma unroll
    for (int rr = 0; rr < 4; rr++) {
        const int row = rr * 8 + r;
        sm[row][c] = W[(size_t)(k0 + row) * DD + n0 + c];
    }
    __syncthreads();
#pragma unroll
    for (int rr = 0; rr < 4; rr++) {
        const int row = rr * 8 + r;
        const float v = sm[c][row];
        __nv_bfloat16 hi = __float2bfloat16(v);
        __nv_bfloat16 lo = __float2bfloat16(v - __bfloat162float(hi));
        Whi[(size_t)(n0 + row) * DD + k0 + c] = hi;
        Wlo[(size_t)(n0 + row) * DD + k0 + c] = lo;
    }
}

// ---------------- HMMA GEMM: C[M,N] = x @ W (fp32 via bf16 3-term split) -----
// EPI=false: C -> g_zlin.   EPI=true: z=sig(zlin+bz), a=1-z, b=z*(C+bh).
template <bool EPI>
__global__ __launch_bounds__(256)
void gemm_mma_kernel(const float* __restrict__ bz, const float* __restrict__ bh)
{
    extern __shared__ char smem[];
    const uint32_t sbase = smem_u32(smem);
    const int tid  = threadIdx.x;
    const int wid  = tid >> 5;
    const int lane = tid & 31;
    const int wr = wid >> 2;           // warp row 0..1 (M)
    const int wc = wid & 3;            // warp col 0..3 (N)

    const int nBase = blockIdx.x * 128;
    const int mBase = blockIdx.y * 128;

    const __nv_bfloat16* wt_hi = EPI ? g_Wth_hi : g_Wtz_hi;
    const __nv_bfloat16* wt_lo = EPI ? g_Wth_lo : g_Wtz_lo;

    // ---- cp.async static addressing: 2 A-chunks + 2 B-chunks of 16B per thread
    int ldRow[2];
    int ldCol[2];
    uint32_t ldOff[2];
#pragma unroll
    for (int t = 0; t < 2; t++) {
        const int o = tid + t * 256;
        ldRow[t] = o >> 2;
        ldCol[t] = o & 3;
        ldOff[t] = SWZ64((uint32_t)(o * 16));
    }

    // ---- ldmatrix static offsets
    const int quad = lane >> 3;
    const int r8   = lane & 7;
    const int rowA = (quad & 1) * 8 + r8;       // A: quads 0/1 rows, 2/3 rows (k+8)
    const int kbA  = (quad >> 1) * 16;
    const int rowB = (quad >> 1) * 8 + r8;      // B: quads 0/1 k-halves, 2/3 n+8
    const int kbB  = (quad & 1) * 16;

    uint32_t offA[2][4], offB[2][2];
#pragma unroll
    for (int ks = 0; ks < 2; ks++) {
#pragma unroll
        for (int mt = 0; mt < 4; mt++)
            offA[ks][mt] = SWZ64((uint32_t)((wr * 64 + mt * 16 + rowA) * 64 + ks * 32 + kbA));
#pragma unroll
        for (int bt = 0; bt < 2; bt++)
            offB[ks][bt] = A_HALF + SWZ64((uint32_t)((wc * 32 + bt * 16 + rowB) * 64 + ks * 32 + kbB));
    }

    float acc[4][4][4];
#pragma unroll
    for (int i = 0; i < 4; i++)
#pragma unroll
        for (int j = 0; j < 4; j++)
#pragma unroll
            for (int k = 0; k < 4; k++) acc[i][j][k] = 0.0f;

    auto load_chunk = [&](int chunk, int stage) {
        const int seg = chunk >> 5;
        const int k0  = (chunk & 31) * BKE;
        const __nv_bfloat16* As = (seg == 2) ? g_alo : g_ahi;
        const __nv_bfloat16* Bs = (seg == 1) ? wt_lo : wt_hi;
        const uint32_t stA = sbase + stage * STAGE_B;
        const uint32_t stB = stA + A_HALF;
#pragma unroll
        for (int t = 0; t < 2; t++) {
            cp16(stA + ldOff[t], As + (size_t)(mBase + ldRow[t]) * DD + k0 + ldCol[t] * 8);
            cp16(stB + ldOff[t], Bs + (size_t)(nBase + ldRow[t]) * DD + k0 + ldCol[t] * 8);
        }
        cp_commit();
    };

    // prologue: 2 chunks in flight
    load_chunk(0, 0);
    load_chunk(1, 1);

    for (int i = 0; i < NCH; i++) {
        const int s = i % 3;
        if (i < NCH - 1) asm volatile("cp.async.wait_group 1;" ::: "memory");
        else             asm volatile("cp.async.wait_group 0;" ::: "memory");
        __syncthreads();
        // stage (i+2)%3 == (i-1)%3 was fully consumed by all warps (sync above)
        if (i + 2 < NCH) load_chunk(i + 2, (i + 2) % 3);

        const uint32_t st = sbase + s * STAGE_B;
#pragma unroll
        for (int ks = 0; ks < 2; ks++) {
            uint32_t af[4][4];
#pragma unroll
            for (int mt = 0; mt < 4; mt++)
                ldsm_x4(af[mt][0], af[mt][1], af[mt][2], af[mt][3], st + offA[ks][mt]);
            uint32_t bf[4][2];
#pragma unroll
            for (int bt = 0; bt < 2; bt++)
                ldsm_x4(bf[bt*2][0], bf[bt*2][1], bf[bt*2+1][0], bf[bt*2+1][1],
                        st + offB[ks][bt]);
#pragma unroll
            for (int mt = 0; mt < 4; mt++)
#pragma unroll
                for (int nt = 0; nt < 4; nt++)
                    mma_bf16(acc[mt][nt], af[mt], bf[nt]);
        }
    }

    // ---- epilogue: D fragment -> gmem
    const int er = lane >> 2;
    const int ec = (lane & 3) * 2;
#pragma unroll
    for (int mt = 0; mt < 4; mt++) {
#pragma unroll
        for (int nt = 0; nt < 4; nt++) {
            const int m = mBase + wr * 64 + mt * 16 + er;
            const int n = nBase + wc * 32 + nt * 8 + ec;
            const size_t g0 = (size_t)m * DD + n;
            const size_t g1 = g0 + 8 * DD;
            if (!EPI) {
                *(float2*)(&g_zlin[g0]) = make_float2(acc[mt][nt][0], acc[mt][nt][1]);
                *(float2*)(&g_zlin[g1]) = make_float2(acc[mt][nt][2], acc[mt][nt][3]);
            } else {
                const float2 bz2 = *(const float2*)(&bz[n]);
                const float2 bh2 = *(const float2*)(&bh[n]);
                const float2 zl0 = *(const float2*)(&g_zlin[g0]);
                const float2 zl1 = *(const float2*)(&g_zlin[g1]);
                float2 av, bv;
                float z;
                z = sigmoidf_fast(zl0.x + bz2.x);
                av.x = 1.0f - z; bv.x = z * (acc[mt][nt][0] + bh2.x);
                z = sigmoidf_fast(zl0.y + bz2.y);
                av.y = 1.0f - z; bv.y = z * (acc[mt][nt][1] + bh2.y);
                *(float2*)(&g_a[g0]) = av;
                *(float2*)(&g_b[g0]) = bv;
                z = sigmoidf_fast(zl1.x + bz2.x);
                av.x = 1.0f - z; bv.x = z * (acc[mt][nt][2] + bh2.x);
                z = sigmoidf_fast(zl1.y + bz2.y);
                av.y = 1.0f - z; bv.y = z * (acc[mt][nt][3] + bh2.y);
                *(float2*)(&g_a[g1]) = av;
                *(float2*)(&g_b[g1]) = bv;
            }
        }
    }
}

// ---------------- scan pass 1 ----------------
__global__ __launch_bounds__(256)
void scan_pass1()
{
    const int g  = blockIdx.x * blockDim.x + threadIdx.x;
    const int d  = g & (DD - 1);
    const int bc = g >> 10;
    const size_t base = ((size_t)bc * CHLEN) * DD + d;
    float Ar = 1.0f, Br = 0.0f;
#pragma unroll 8
    for (int t = 0; t < CHLEN; t++) {
        const float a  = g_a[base + (size_t)t * DD];
        const float bb = g_b[base + (size_t)t * DD];
        Br = fmaf(a, Br, bb);
        Ar *= a;
    }
    g_Ac[g] = Ar;
    g_Bc[g] = Br;
}

// ---------------- scan pass 2 ----------------
__global__ __launch_bounds__(256)
void scan_pass2()
{
    const int g = blockIdx.x * blockDim.x + threadIdx.x;
    const int d = g & (DD - 1);
    const int b = g >> 10;
    float h = 0.0f;
#pragma unroll
    for (int c = 0; c < NCHUNK; c++) {
        const int idx = (b * NCHUNK + c) * DD + d;
        g_hinit[idx] = h;
        h = fmaf(g_Ac[idx], h, g_Bc[idx]);
    }
}

// ---------------- scan pass 3 + swish ----------------
__global__ __launch_bounds__(256)
void scan_pass3(const float* __restrict__ swish_beta)
{
    const int g  = blockIdx.x * blockDim.x + threadIdx.x;
    const int d  = g & (DD - 1);
    const int bc = g >> 10;
    const size_t base = ((size_t)bc * CHLEN) * DD + d;
    const float beta = __ldg(swish_beta);
    float h = g_hinit[g];
#pragma unroll 8
    for (int t = 0; t < CHLEN; t++) {
        const size_t idx = base + (size_t)t * DD;
        h = fmaf(g_a[idx], h, g_b[idx]);
        const float s = beta * h;
        g_zlin[idx] = s * sigmoidf_fast(s);
    }
}

// ---------------- LayerNorm ----------------
__global__ __launch_bounds__(256)
void ln_kernel(float* __restrict__ out,
               const float* __restrict__ gamma,
               const float* __restrict__ lbeta)
{
    const int row = blockIdx.x;
    const int tid = threadIdx.x;
    const float4 v = ((const float4*)(g_zlin + (size_t)row * DD))[tid];
    float s  = v.x + v.y + v.z + v.w;
    float sq = v.x * v.x + v.y * v.y + v.z * v.z + v.w * v.w;
#pragma unroll
    for (int o = 16; o > 0; o >>= 1) {
        s  += __shfl_xor_sync(0xffffffffu, s, o);
        sq += __shfl_xor_sync(0xffffffffu, sq, o);
    }
    __shared__ float sa[8], sb[8];
    const int w = tid >> 5, l = tid & 31;
    if (l == 0) { sa[w] = s; sb[w] = sq; }
    __syncthreads();
    if (w == 0) {
        s  = (l < 8) ? sa[l] : 0.0f;
        sq = (l < 8) ? sb[l] : 0.0f;
#pragma unroll
        for (int o = 4; o > 0; o >>= 1) {
            s  += __shfl_xor_sync(0xffffffffu, s, o);
            sq += __shfl_xor_sync(0xffffffffu, sq, o);
        }
        if (l == 0) { sa[0] = s; sb[0] = sq; }
    }
    __syncthreads();
    const float mu  = sa[0] * (1.0f / DD);
    const float var = sb[0] * (1.0f / DD) - mu * mu;
    const float inv = rsqrtf(var + 1e-5f);
    const float4 gm = ((const float4*)gamma)[tid];
    const float4 bt = ((const float4*)lbeta)[tid];
    float4 o;
    o.x = (v.x - mu) * inv * gm.x + bt.x;
    o.y = (v.y - mu) * inv * gm.y + bt.y;
    o.z = (v.z - mu) * inv * gm.z + bt.z;
    o.w = (v.w - mu) * inv * gm.w + bt.w;
    ((float4*)(out + (size_t)row * DD))[tid] = o;
}

// ---------------- launch ----------------
extern "C" void kernel_launch(void* const* d_in, const int* in_sizes, int n_in,
                              void* d_out, int out_size)
{
    const float* x     = (const float*)d_in[0];
    const float* Wz    = (const float*)d_in[1];
    const float* bz    = (const float*)d_in[2];
    const float* Wh    = (const float*)d_in[3];
    const float* bh    = (const float*)d_in[4];
    const float* sbeta = (const float*)d_in[5];
    const float* gamma = (const float*)d_in[6];
    const float* lbeta = (const float*)d_in[7];
    float* out = (float*)d_out;

    split_x_kernel<<<(MM * DD) / (256 * 4), 256>>>(x);
    transpose_split_kernel<<<dim3(32, 32, 2), 256>>>(Wz, Wh);

    dim3 gemmGrid(DD / 128, MM / 128);   // (8, 128)
    gemm_mma_kernel<false><<<gemmGrid, 256, SMEM_GEMM>>>(nullptr, nullptr);
    gemm_mma_kernel<true ><<<gemmGrid, 256, SMEM_GEMM>>>(bz, bh);

    scan_pass1<<<(BB * NCHUNK * DD) / 256, 256>>>();
    scan_pass2<<<(BB * DD) / 256, 256>>>();
    scan_pass3<<<(BB * NCHUNK * DD) / 256, 256>>>(sbeta);

    ln_kernel<<<MM, 256>>>(out, gamma, lbeta);
}

// round 4
// speedup vs baseline: 2.6006x; 1.0275x over previous
#include <cuda_runtime.h>
#include <cuda_bf16.h>
#include <math.h>
#include <stdint.h>

// Problem shape (fixed): B=8, T=2048, D=1024
#define BB   8
#define TT   2048
#define DD   1024
#define MM   (BB*TT)          // 16384 rows
#define NCHUNK 32
#define CHLEN  64

// Fused GEMM tiling: CTA 128(M)x128(N) x 2 outputs, warp 64x32x2, BK=32
#define BKE    32             // K elements per chunk (64B rows in smem)
#define NCH    96             // 3 segs * 32 chunks (K=3072 split)
#define A_OFF  0
#define BZ_OFF 8192
#define BH_OFF 16384
#define STAGE_B 24576          // 24KB per stage (A + Bz + Bh)
#define SMEM_GEMM (2 * STAGE_B) // 49152 = 48KB (default dynamic limit, no attr)

// ---------------- scratch (device globals) ----------------
__device__ float g_y[(size_t)MM * DD];      // swish output / LN input
__device__ float g_a[(size_t)MM * DD];
__device__ float g_b[(size_t)MM * DD];
__device__ float g_Ac[BB * NCHUNK * DD];
__device__ float g_Bc[BB * NCHUNK * DD];
__device__ float g_hinit[BB * NCHUNK * DD];

__device__ __nv_bfloat16 g_ahi[(size_t)MM * DD];
__device__ __nv_bfloat16 g_alo[(size_t)MM * DD];
__device__ __nv_bfloat16 g_Wtz_hi[DD * DD];
__device__ __nv_bfloat16 g_Wtz_lo[DD * DD];
__device__ __nv_bfloat16 g_Wth_hi[DD * DD];
__device__ __nv_bfloat16 g_Wth_lo[DD * DD];

__device__ __forceinline__ float sigmoidf_fast(float v) {
    return 1.0f / (1.0f + __expf(-v));
}

// ---------------- PTX helpers ----------------
__device__ __forceinline__ uint32_t smem_u32(const void* p) {
    uint32_t a;
    asm("{ .reg .u64 t; cvta.to.shared.u64 t, %1; cvt.u32.u64 %0, t; }" : "=r"(a) : "l"(p));
    return a;
}
#define SWZ64(o) ((o) ^ (((o) >> 3) & 0x30))

__device__ __forceinline__ void cp16(uint32_t s, const void* g) {
    asm volatile("cp.async.cg.shared.global [%0], [%1], 16;" :: "r"(s), "l"(g));
}
__device__ __forceinline__ void cp_commit() {
    asm volatile("cp.async.commit_group;" ::: "memory");
}
__device__ __forceinline__ void ldsm_x4(uint32_t& r0, uint32_t& r1, uint32_t& r2,
                                        uint32_t& r3, uint32_t addr) {
    asm volatile("ldmatrix.sync.aligned.m8n8.x4.shared.b16 {%0,%1,%2,%3}, [%4];"
                 : "=r"(r0), "=r"(r1), "=r"(r2), "=r"(r3) : "r"(addr));
}
__device__ __forceinline__ void mma_bf16(float* d, const uint32_t* a, const uint32_t* b) {
    asm volatile(
        "mma.sync.aligned.m16n8k16.row.col.f32.bf16.bf16.f32 "
        "{%0,%1,%2,%3},{%4,%5,%6,%7},{%8,%9},{%0,%1,%2,%3};"
        : "+f"(d[0]), "+f"(d[1]), "+f"(d[2]), "+f"(d[3])
        : "r"(a[0]), "r"(a[1]), "r"(a[2]), "r"(a[3]), "r"(b[0]), "r"(b[1]));
}

// ---------------- prep: split x into hi/lo bf16 ----------------
__global__ __launch_bounds__(256)
void split_x_kernel(const float* __restrict__ x)
{
    const size_t i4 = (size_t)blockIdx.x * 256 + threadIdx.x;
    const float4 v = ((const float4*)x)[i4];
    __nv_bfloat16 h0 = __float2bfloat16(v.x);
    __nv_bfloat16 h1 = __float2bfloat16(v.y);
    __nv_bfloat16 h2 = __float2bfloat16(v.z);
    __nv_bfloat16 h3 = __float2bfloat16(v.w);
    __nv_bfloat162 hi0, hi1, lo0, lo1;
    hi0.x = h0; hi0.y = h1; hi1.x = h2; hi1.y = h3;
    lo0.x = __float2bfloat16(v.x - __bfloat162float(h0));
    lo0.y = __float2bfloat16(v.y - __bfloat162float(h1));
    lo1.x = __float2bfloat16(v.z - __bfloat162float(h2));
    lo1.y = __float2bfloat16(v.w - __bfloat162float(h3));
    ((__nv_bfloat162*)g_ahi)[i4 * 2]     = hi0;
    ((__nv_bfloat162*)g_ahi)[i4 * 2 + 1] = hi1;
    ((__nv_bfloat162*)g_alo)[i4 * 2]     = lo0;
    ((__nv_bfloat162*)g_alo)[i4 * 2 + 1] = lo1;
}

// ---------------- prep: transpose + split W -> Wt[n][k] hi/lo ----------------
__global__ __launch_bounds__(256)
void transpose_split_kernel(const float* __restrict__ Wz, const float* __restrict__ Wh)
{
    __shared__ float sm[32][33];
    const float* W = (blockIdx.z == 0) ? Wz : Wh;
    __nv_bfloat16* Whi = (blockIdx.z == 0) ? g_Wtz_hi : g_Wth_hi;
    __nv_bfloat16* Wlo = (blockIdx.z == 0) ? g_Wtz_lo : g_Wth_lo;

    const int k0 = blockIdx.y * 32;
    const int n0 = blockIdx.x * 32;
    const int r = threadIdx.x >> 5;
    const int c = threadIdx.x & 31;
#pragma unroll
    for (int rr = 0; rr < 4; rr++) {
        const int row = rr * 8 + r;
        sm[row][c] = W[(size_t)(k0 + row) * DD + n0 + c];
    }
    __syncthreads();
#pragma unroll
    for (int rr = 0; rr < 4; rr++) {
        const int row = rr * 8 + r;
        const float v = sm[c][row];
        __nv_bfloat16 hi = __float2bfloat16(v);
        __nv_bfloat16 lo = __float2bfloat16(v - __bfloat162float(hi));
        Whi[(size_t)(n0 + row) * DD + k0 + c] = hi;
        Wlo[(size_t)(n0 + row) * DD + k0 + c] = lo;
    }
}

// ---------------- fused HMMA GEMM: zlin = x@Wz, hlin = x@Wh ------------------
// epilogue: z = sig(zlin+bz); g_a = 1-z; g_b = z*(hlin+bh).
__global__ __launch_bounds__(256, 1)
void gemm_fused_kernel(const float* __restrict__ bz, const float* __restrict__ bh)
{
    extern __shared__ char smem[];
    const uint32_t sbase = smem_u32(smem);
    const int tid  = threadIdx.x;
    const int wid  = tid >> 5;
    const int lane = tid & 31;
    const int wr = wid >> 2;           // warp row 0..1 (64 M-rows each)
    const int wc = wid & 3;            // warp col 0..3 (32 N-cols each)

    const int nBase = blockIdx.x * 128;
    const int mBase = blockIdx.y * 128;

    // ---- cp.async static addressing: per region, 2x 16B per thread ----
    int ldRow[2];
    int ldCol[2];
    uint32_t ldOff[2];
#pragma unroll
    for (int t = 0; t < 2; t++) {
        const int o = tid + t * 256;
        ldRow[t] = o >> 2;             // 128 rows x 4 chunks of 16B (64B rows)
        ldCol[t] = o & 3;
        ldOff[t] = SWZ64((uint32_t)(o * 16));
    }

    // ---- ldmatrix static offsets ----
    const int quad = lane >> 3;
    const int r8   = lane & 7;
    const int rowA = (quad & 1) * 8 + r8;
    const int kbA  = (quad >> 1) * 16;
    const int rowB = (quad >> 1) * 8 + r8;
    const int kbB  = (quad & 1) * 16;

    uint32_t offA[2][4], offB[2][2];   // offB relative to B region start
#pragma unroll
    for (int ks = 0; ks < 2; ks++) {
#pragma unroll
        for (int mt = 0; mt < 4; mt++)
            offA[ks][mt] = SWZ64((uint32_t)((wr * 64 + mt * 16 + rowA) * 64 + ks * 32 + kbA));
#pragma unroll
        for (int bt = 0; bt < 2; bt++)
            offB[ks][bt] = SWZ64((uint32_t)((wc * 32 + bt * 16 + rowB) * 64 + ks * 32 + kbB));
    }

    float accz[4][4][4], acch[4][4][4];
#pragma unroll
    for (int i = 0; i < 4; i++)
#pragma unroll
        for (int j = 0; j < 4; j++)
#pragma unroll
            for (int k = 0; k < 4; k++) { accz[i][j][k] = 0.0f; acch[i][j][k] = 0.0f; }

    auto load_chunk = [&](int chunk, int stage) {
        const int seg = chunk >> 5;                 // 0: hi*hi, 1: hi*lo, 2: lo*hi
        const int k0  = (chunk & 31) * BKE;
        const __nv_bfloat16* As  = (seg == 2) ? g_alo : g_ahi;
        const __nv_bfloat16* Bzs = (seg == 1) ? g_Wtz_lo : g_Wtz_hi;
        const __nv_bfloat16* Bhs = (seg == 1) ? g_Wth_lo : g_Wth_hi;
        const uint32_t st = sbase + stage * STAGE_B;
#pragma unroll
        for (int t = 0; t < 2; t++) {
            const size_t rowOff = (size_t)ldRow[t] * DD + k0 + ldCol[t] * 8;
            cp16(st + A_OFF  + ldOff[t], As  + (size_t)mBase * DD + rowOff);
            cp16(st + BZ_OFF + ldOff[t], Bzs + (size_t)nBase * DD + rowOff);
            cp16(st + BH_OFF + ldOff[t], Bhs + (size_t)nBase * DD + rowOff);
        }
        cp_commit();
    };

    // prologue: 1 chunk in flight
    load_chunk(0, 0);

    for (int i = 0; i < NCH; i++) {
        const int s = i & 1;
        if (i + 1 < NCH) {
            load_chunk(i + 1, s ^ 1);
            asm volatile("cp.async.wait_group 1;" ::: "memory");
        } else {
            asm volatile("cp.async.wait_group 0;" ::: "memory");
        }
        __syncthreads();

        const uint32_t st = sbase + s * STAGE_B;
#pragma unroll
        for (int ks = 0; ks < 2; ks++) {
            uint32_t af[4][4];
#pragma unroll
            for (int mt = 0; mt < 4; mt++)
                ldsm_x4(af[mt][0], af[mt][1], af[mt][2], af[mt][3],
                        st + A_OFF + offA[ks][mt]);
            // ---- z output ----
            {
                uint32_t bf[4][2];
#pragma unroll
                for (int bt = 0; bt < 2; bt++)
                    ldsm_x4(bf[bt*2][0], bf[bt*2][1], bf[bt*2+1][0], bf[bt*2+1][1],
                            st + BZ_OFF + offB[ks][bt]);
#pragma unroll
                for (int mt = 0; mt < 4; mt++)
#pragma unroll
                    for (int nt = 0; nt < 4; nt++)
                        mma_bf16(accz[mt][nt], af[mt], bf[nt]);
            }
            // ---- h output ----
            {
                uint32_t bf[4][2];
#pragma unroll
                for (int bt = 0; bt < 2; bt++)
                    ldsm_x4(bf[bt*2][0], bf[bt*2][1], bf[bt*2+1][0], bf[bt*2+1][1],
                            st + BH_OFF + offB[ks][bt]);
#pragma unroll
                for (int mt = 0; mt < 4; mt++)
#pragma unroll
                    for (int nt = 0; nt < 4; nt++)
                        mma_bf16(acch[mt][nt], af[mt], bf[nt]);
            }
        }
        // next iteration's __syncthreads (after its load issue) protects stage reuse
    }

    // ---- epilogue: a = 1-z, b = z*(hlin+bh) directly from fragments ----
    const int er = lane >> 2;
    const int ec = (lane & 3) * 2;
#pragma unroll
    for (int mt = 0; mt < 4; mt++) {
#pragma unroll
        for (int nt = 0; nt < 4; nt++) {
            const int m = mBase + wr * 64 + mt * 16 + er;
            const int n = nBase + wc * 32 + nt * 8 + ec;
            const size_t g0 = (size_t)m * DD + n;
            const size_t g1 = g0 + 8 * DD;
            const float2 bz2 = *(const float2*)(&bz[n]);
            const float2 bh2 = *(const float2*)(&bh[n]);
            float2 av, bv;
            float z;
            z = sigmoidf_fast(accz[mt][nt][0] + bz2.x);
            av.x = 1.0f - z; bv.x = z * (acch[mt][nt][0] + bh2.x);
            z = sigmoidf_fast(accz[mt][nt][1] + bz2.y);
            av.y = 1.0f - z; bv.y = z * (acch[mt][nt][1] + bh2.y);
            *(float2*)(&g_a[g0]) = av;
            *(float2*)(&g_b[g0]) = bv;
            z = sigmoidf_fast(accz[mt][nt][2] + bz2.x);
            av.x = 1.0f - z; bv.x = z * (acch[mt][nt][2] + bh2.x);
            z = sigmoidf_fast(accz[mt][nt][3] + bz2.y);
            av.y = 1.0f - z; bv.y = z * (acch[mt][nt][3] + bh2.y);
            *(float2*)(&g_a[g1]) = av;
            *(float2*)(&g_b[g1]) = bv;
        }
    }
}

// ---------------- scan pass 1 ----------------
__global__ __launch_bounds__(256)
void scan_pass1()
{
    const int g  = blockIdx.x * blockDim.x + threadIdx.x;
    const int d  = g & (DD - 1);
    const int bc = g >> 10;
    const size_t base = ((size_t)bc * CHLEN) * DD + d;
    float Ar = 1.0f, Br = 0.0f;
#pragma unroll 8
    for (int t = 0; t < CHLEN; t++) {
        const float a  = g_a[base + (size_t)t * DD];
        const float bb = g_b[base + (size_t)t * DD];
        Br = fmaf(a, Br, bb);
        Ar *= a;
    }
    g_Ac[g] = Ar;
    g_Bc[g] = Br;
}

// ---------------- scan pass 2 ----------------
__global__ __launch_bounds__(256)
void scan_pass2()
{
    const int g = blockIdx.x * blockDim.x + threadIdx.x;
    const int d = g & (DD - 1);
    const int b = g >> 10;
    float h = 0.0f;
#pragma unroll
    for (int c = 0; c < NCHUNK; c++) {
        const int idx = (b * NCHUNK + c) * DD + d;
        g_hinit[idx] = h;
        h = fmaf(g_Ac[idx], h, g_Bc[idx]);
    }
}

// ---------------- scan pass 3 + swish ----------------
__global__ __launch_bounds__(256)
void scan_pass3(const float* __restrict__ swish_beta)
{
    const int g  = blockIdx.x * blockDim.x + threadIdx.x;
    const int d  = g & (DD - 1);
    const int bc = g >> 10;
    const size_t base = ((size_t)bc * CHLEN) * DD + d;
    const float beta = __ldg(swish_beta);
    float h = g_hinit[g];
#pragma unroll 8
    for (int t = 0; t < CHLEN; t++) {
        const size_t idx = base + (size_t)t * DD;
        h = fmaf(g_a[idx], h, g_b[idx]);
        const float s = beta * h;
        g_y[idx] = s * sigmoidf_fast(s);
    }
}

// ---------------- LayerNorm ----------------
__global__ __launch_bounds__(256)
void ln_kernel(float* __restrict__ out,
               const float* __restrict__ gamma,
               const float* __restrict__ lbeta)
{
    const int row = blockIdx.x;
    const int tid = threadIdx.x;
    const float4 v = ((const float4*)(g_y + (size_t)row * DD))[tid];
    float s  = v.x + v.y + v.z + v.w;
    float sq = v.x * v.x + v.y * v.y + v.z * v.z + v.w * v.w;
#pragma unroll
    for (int o = 16; o > 0; o >>= 1) {
        s  += __shfl_xor_sync(0xffffffffu, s, o);
        sq += __shfl_xor_sync(0xffffffffu, sq, o);
    }
    __shared__ float sa[8], sb[8];
    const int w = tid >> 5, l = tid & 31;
    if (l == 0) { sa[w] = s; sb[w] = sq; }
    __syncthreads();
    if (w == 0) {
        s  = (l < 8) ? sa[l] : 0.0f;
        sq = (l < 8) ? sb[l] : 0.0f;
#pragma unroll
        for (int o = 4; o > 0; o >>= 1) {
            s  += __shfl_xor_sync(0xffffffffu, s, o);
            sq += __shfl_xor_sync(0xffffffffu, sq, o);
        }
        if (l == 0) { sa[0] = s; sb[0] = sq; }
    }
    __syncthreads();
    const float mu  = sa[0] * (1.0f / DD);
    const float var = sb[0] * (1.0f / DD) - mu * mu;
    const float inv = rsqrtf(var + 1e-5f);
    const float4 gm = ((const float4*)gamma)[tid];
    const float4 bt = ((const float4*)lbeta)[tid];
    float4 o;
    o.x = (v.x - mu) * inv * gm.x + bt.x;
    o.y = (v.y - mu) * inv * gm.y + bt.y;
    o.z = (v.z - mu) * inv * gm.z + bt.z;
    o.w = (v.w - mu) * inv * gm.w + bt.w;
    ((float4*)(out + (size_t)row * DD))[tid] = o;
}

// ---------------- launch ----------------
extern "C" void kernel_launch(void* const* d_in, const int* in_sizes, int n_in,
                              void* d_out, int out_size)
{
    const float* x     = (const float*)d_in[0];
    const float* Wz    = (const float*)d_in[1];
    const float* bz    = (const float*)d_in[2];
    const float* Wh    = (const float*)d_in[3];
    const float* bh    = (const float*)d_in[4];
    const float* sbeta = (const float*)d_in[5];
    const float* gamma = (const float*)d_in[6];
    const float* lbeta = (const float*)d_in[7];
    float* out = (float*)d_out;

    split_x_kernel<<<(MM * DD) / (256 * 4), 256>>>(x);
    transpose_split_kernel<<<dim3(32, 32, 2), 256>>>(Wz, Wh);

    dim3 gemmGrid(DD / 128, MM / 128);   // (8, 128)
    gemm_fused_kernel<<<gemmGrid, 256, SMEM_GEMM>>>(bz, bh);

    scan_pass1<<<(BB * NCHUNK * DD) / 256, 256>>>();
    scan_pass2<<<(BB * DD) / 256, 256>>>();
    scan_pass3<<<(BB * NCHUNK * DD) / 256, 256>>>(sbeta);

    ln_kernel<<<MM, 256>>>(out, gamma, lbeta);
}

// round 5
// speedup vs baseline: 5.0630x; 1.9469x over previous
#include <cuda_runtime.h>
#include <cuda_fp16.h>
#include <math.h>
#include <stdint.h>

// Problem shape (fixed): B=8, T=2048, D=1024
#define BB   8
#define TT   2048
#define DD   1024
#define MM   (BB*TT)          // 16384 rows
#define NCHUNK 32
#define CHLEN  64

// Fused GEMM tiling: CTA 128(M)x128(N), 2 outputs, warp 64x32x2, BK=32, K=1024
#define BKE    32             // K elements per chunk (64B rows in smem)
#define NCH    (DD / BKE)     // 32 chunks
#define A_OFF  0
#define BZ_OFF 8192
#define BH_OFF 16384
#define STAGE_B 24576          // 24KB per stage (A + Bz + Bh)
#define SMEM_GEMM (2 * STAGE_B) // 48KB (default dynamic limit, no attr call)

// ---------------- scratch (device globals) ----------------
__device__ float g_y[(size_t)MM * DD];      // swish output / LN input
__device__ float g_a[(size_t)MM * DD];
__device__ float g_b[(size_t)MM * DD];
__device__ float g_Ac[BB * NCHUNK * DD];
__device__ float g_Bc[BB * NCHUNK * DD];
__device__ float g_hinit[BB * NCHUNK * DD];

__device__ __half g_xh[(size_t)MM * DD];    // x in fp16
__device__ __half g_Wtz[DD * DD];           // Wz^T in fp16: [n][k]
__device__ __half g_Wth[DD * DD];           // Wh^T in fp16: [n][k]

__device__ __forceinline__ float sigmoidf_fast(float v) {
    return 1.0f / (1.0f + __expf(-v));
}

// ---------------- PTX helpers ----------------
__device__ __forceinline__ uint32_t smem_u32(const void* p) {
    uint32_t a;
    asm("{ .reg .u64 t; cvta.to.shared.u64 t, %1; cvt.u32.u64 %0, t; }" : "=r"(a) : "l"(p));
    return a;
}
#define SWZ64(o) ((o) ^ (((o) >> 3) & 0x30))

__device__ __forceinline__ void cp16(uint32_t s, const void* g) {
    asm volatile("cp.async.cg.shared.global [%0], [%1], 16;" :: "r"(s), "l"(g));
}
__device__ __forceinline__ void cp_commit() {
    asm volatile("cp.async.commit_group;" ::: "memory");
}
__device__ __forceinline__ void ldsm_x4(uint32_t& r0, uint32_t& r1, uint32_t& r2,
                                        uint32_t& r3, uint32_t addr) {
    asm volatile("ldmatrix.sync.aligned.m8n8.x4.shared.b16 {%0,%1,%2,%3}, [%4];"
                 : "=r"(r0), "=r"(r1), "=r"(r2), "=r"(r3) : "r"(addr));
}
__device__ __forceinline__ void mma_f16(float* d, const uint32_t* a, const uint32_t* b) {
    asm volatile(
        "mma.sync.aligned.m16n8k16.row.col.f32.f16.f16.f32 "
        "{%0,%1,%2,%3},{%4,%5,%6,%7},{%8,%9},{%0,%1,%2,%3};"
        : "+f"(d[0]), "+f"(d[1]), "+f"(d[2]), "+f"(d[3])
        : "r"(a[0]), "r"(a[1]), "r"(a[2]), "r"(a[3]), "r"(b[0]), "r"(b[1]));
}

// ---------------- prep: convert x to fp16 ----------------
__global__ __launch_bounds__(256)
void convert_x_kernel(const float* __restrict__ x)
{
    const size_t i4 = (size_t)blockIdx.x * 256 + threadIdx.x;
    const float4 v = ((const float4*)x)[i4];
    __half2 p0, p1;
    p0.x = __float2half_rn(v.x); p0.y = __float2half_rn(v.y);
    p1.x = __float2half_rn(v.z); p1.y = __float2half_rn(v.w);
    ((__half2*)g_xh)[i4 * 2]     = p0;
    ((__half2*)g_xh)[i4 * 2 + 1] = p1;
}

// ---------------- prep: transpose W -> Wt[n][k], fp16 ----------------
__global__ __launch_bounds__(256)
void transpose_kernel(const float* __restrict__ Wz, const float* __restrict__ Wh)
{
    __shared__ float sm[32][33];
    const float* W = (blockIdx.z == 0) ? Wz : Wh;
    __half* Wt = (blockIdx.z == 0) ? g_Wtz : g_Wth;

    const int k0 = blockIdx.y * 32;
    const int n0 = blockIdx.x * 32;
    const int r = threadIdx.x >> 5;
    const int c = threadIdx.x & 31;
#pragma unroll
    for (int rr = 0; rr < 4; rr++) {
        const int row = rr * 8 + r;
        sm[row][c] = W[(size_t)(k0 + row) * DD + n0 + c];
    }
    __syncthreads();
#pragma unroll
    for (int rr = 0; rr < 4; rr++) {
        const int row = rr * 8 + r;
        Wt[(size_t)(n0 + row) * DD + k0 + c] = __float2half_rn(sm[c][row]);
    }
}

// ---------------- fused HMMA GEMM: zlin = x@Wz, hlin = x@Wh ------------------
// epilogue: z = sig(zlin+bz); g_a = 1-z; g_b = z*(hlin+bh).
__global__ __launch_bounds__(256, 1)
void gemm_fused_kernel(const float* __restrict__ bz, const float* __restrict__ bh)
{
    extern __shared__ char smem[];
    const uint32_t sbase = smem_u32(smem);
    const int tid  = threadIdx.x;
    const int wid  = tid >> 5;
    const int lane = tid & 31;
    const int wr = wid >> 2;           // warp row 0..1 (64 M-rows each)
    const int wc = wid & 3;            // warp col 0..3 (32 N-cols each)

    const int nBase = blockIdx.x * 128;
    const int mBase = blockIdx.y * 128;

    // ---- cp.async static addressing: per region, 2x 16B per thread ----
    int ldRow[2];
    int ldCol[2];
    uint32_t ldOff[2];
#pragma unroll
    for (int t = 0; t < 2; t++) {
        const int o = tid + t * 256;
        ldRow[t] = o >> 2;             // 128 rows x 4 chunks of 16B (64B rows)
        ldCol[t] = o & 3;
        ldOff[t] = SWZ64((uint32_t)(o * 16));
    }

    // ---- ldmatrix static offsets ----
    const int quad = lane >> 3;
    const int r8   = lane & 7;
    const int rowA = (quad & 1) * 8 + r8;
    const int kbA  = (quad >> 1) * 16;
    const int rowB = (quad >> 1) * 8 + r8;
    const int kbB  = (quad & 1) * 16;

    uint32_t offA[2][4], offB[2][2];   // offB relative to B region start
#pragma unroll
    for (int ks = 0; ks < 2; ks++) {
#pragma unroll
        for (int mt = 0; mt < 4; mt++)
            offA[ks][mt] = SWZ64((uint32_t)((wr * 64 + mt * 16 + rowA) * 64 + ks * 32 + kbA));
#pragma unroll
        for (int bt = 0; bt < 2; bt++)
            offB[ks][bt] = SWZ64((uint32_t)((wc * 32 + bt * 16 + rowB) * 64 + ks * 32 + kbB));
    }

    float accz[4][4][4], acch[4][4][4];
#pragma unroll
    for (int i = 0; i < 4; i++)
#pragma unroll
        for (int j = 0; j < 4; j++)
#pragma unroll
            for (int k = 0; k < 4; k++) { accz[i][j][k] = 0.0f; acch[i][j][k] = 0.0f; }

    auto load_chunk = [&](int chunk, int stage) {
        const int k0 = chunk * BKE;
        const uint32_t st = sbase + stage * STAGE_B;
#pragma unroll
        for (int t = 0; t < 2; t++) {
            const size_t rowOff = (size_t)ldRow[t] * DD + k0 + ldCol[t] * 8;
            cp16(st + A_OFF  + ldOff[t], g_xh  + (size_t)mBase * DD + rowOff);
            cp16(st + BZ_OFF + ldOff[t], g_Wtz + (size_t)nBase * DD + rowOff);
            cp16(st + BH_OFF + ldOff[t], g_Wth + (size_t)nBase * DD + rowOff);
        }
        cp_commit();
    };

    // prologue: 1 chunk in flight
    load_chunk(0, 0);

    for (int i = 0; i < NCH; i++) {
        const int s = i & 1;
        // chunk i's data complete (it's the only outstanding group)
        asm volatile("cp.async.wait_group 0;" ::: "memory");
        // sync AFTER wait, BEFORE next load: guarantees all warps finished
        // reading stage s^1 (iteration i-1's compute) before we overwrite it,
        // and makes chunk i's smem writes visible to all warps.
        __syncthreads();
        if (i + 1 < NCH) load_chunk(i + 1, s ^ 1);   // overlaps compute below

        const uint32_t st = sbase + s * STAGE_B;
#pragma unroll
        for (int ks = 0; ks < 2; ks++) {
            uint32_t af[4][4];
#pragma unroll
            for (int mt = 0; mt < 4; mt++)
                ldsm_x4(af[mt][0], af[mt][1], af[mt][2], af[mt][3],
                        st + A_OFF + offA[ks][mt]);
            // ---- z output ----
            {
                uint32_t bf[4][2];
#pragma unroll
                for (int bt = 0; bt < 2; bt++)
                    ldsm_x4(bf[bt*2][0], bf[bt*2][1], bf[bt*2+1][0], bf[bt*2+1][1],
                            st + BZ_OFF + offB[ks][bt]);
#pragma unroll
                for (int mt = 0; mt < 4; mt++)
#pragma unroll
                    for (int nt = 0; nt < 4; nt++)
                        mma_f16(accz[mt][nt], af[mt], bf[nt]);
            }
            // ---- h output ----
            {
                uint32_t bf[4][2];
#pragma unroll
                for (int bt = 0; bt < 2; bt++)
                    ldsm_x4(bf[bt*2][0], bf[bt*2][1], bf[bt*2+1][0], bf[bt*2+1][1],
                            st + BH_OFF + offB[ks][bt]);
#pragma unroll
                for (int mt = 0; mt < 4; mt++)
#pragma unroll
                    for (int nt = 0; nt < 4; nt++)
                        mma_f16(acch[mt][nt], af[mt], bf[nt]);
            }
        }
    }

    // ---- epilogue: a = 1-z, b = z*(hlin+bh) directly from fragments ----
    const int er = lane >> 2;
    const int ec = (lane & 3) * 2;
#pragma unroll
    for (int mt = 0; mt < 4; mt++) {
#pragma unroll
        for (int nt = 0; nt < 4; nt++) {
            const int m = mBase + wr * 64 + mt * 16 + er;
            const int n = nBase + wc * 32 + nt * 8 + ec;
            const size_t g0 = (size_t)m * DD + n;
            const size_t g1 = g0 + 8 * DD;
            const float2 bz2 = *(const float2*)(&bz[n]);
            const float2 bh2 = *(const float2*)(&bh[n]);
            float2 av, bv;
            float z;
            z = sigmoidf_fast(accz[mt][nt][0] + bz2.x);
            av.x = 1.0f - z; bv.x = z * (acch[mt][nt][0] + bh2.x);
            z = sigmoidf_fast(accz[mt][nt][1] + bz2.y);
            av.y = 1.0f - z; bv.y = z * (acch[mt][nt][1] + bh2.y);
            *(float2*)(&g_a[g0]) = av;
            *(float2*)(&g_b[g0]) = bv;
            z = sigmoidf_fast(accz[mt][nt][2] + bz2.x);
            av.x = 1.0f - z; bv.x = z * (acch[mt][nt][2] + bh2.x);
            z = sigmoidf_fast(accz[mt][nt][3] + bz2.y);
            av.y = 1.0f - z; bv.y = z * (acch[mt][nt][3] + bh2.y);
            *(float2*)(&g_a[g1]) = av;
            *(float2*)(&g_b[g1]) = bv;
        }
    }
}

// ---------------- scan pass 1 ----------------
__global__ __launch_bounds__(256)
void scan_pass1()
{
    const int g  = blockIdx.x * blockDim.x + threadIdx.x;
    const int d  = g & (DD - 1);
    const int bc = g >> 10;
    const size_t base = ((size_t)bc * CHLEN) * DD + d;
    float Ar = 1.0f, Br = 0.0f;
#pragma unroll 8
    for (int t = 0; t < CHLEN; t++) {
        const float a  = g_a[base + (size_t)t * DD];
        const float bb = g_b[base + (size_t)t * DD];
        Br = fmaf(a, Br, bb);
        Ar *= a;
    }
    g_Ac[g] = Ar;
    g_Bc[g] = Br;
}

// ---------------- scan pass 2 ----------------
__global__ __launch_bounds__(256)
void scan_pass2()
{
    const int g = blockIdx.x * blockDim.x + threadIdx.x;
    const int d = g & (DD - 1);
    const int b = g >> 10;
    float h = 0.0f;
#pragma unroll
    for (int c = 0; c < NCHUNK; c++) {
        const int idx = (b * NCHUNK + c) * DD + d;
        g_hinit[idx] = h;
        h = fmaf(g_Ac[idx], h, g_Bc[idx]);
    }
}

// ---------------- scan pass 3 + swish ----------------
__global__ __launch_bounds__(256)
void scan_pass3(const float* __restrict__ swish_beta)
{
    const int g  = blockIdx.x * blockDim.x + threadIdx.x;
    const int d  = g & (DD - 1);
    const int bc = g >> 10;
    const size_t base = ((size_t)bc * CHLEN) * DD + d;
    const float beta = __ldg(swish_beta);
    float h = g_hinit[g];
#pragma unroll 8
    for (int t = 0; t < CHLEN; t++) {
        const size_t idx = base + (size_t)t * DD;
        h = fmaf(g_a[idx], h, g_b[idx]);
        const float s = beta * h;
        g_y[idx] = s * sigmoidf_fast(s);
    }
}

// ---------------- LayerNorm ----------------
__global__ __launch_bounds__(256)
void ln_kernel(float* __restrict__ out,
               const float* __restrict__ gamma,
               const float* __restrict__ lbeta)
{
    const int row = blockIdx.x;
    const int tid = threadIdx.x;
    const float4 v = ((const float4*)(g_y + (size_t)row * DD))[tid];
    float s  = v.x + v.y + v.z + v.w;
    float sq = v.x * v.x + v.y * v.y + v.z * v.z + v.w * v.w;
#pragma unroll
    for (int o = 16; o > 0; o >>= 1) {
        s  += __shfl_xor_sync(0xffffffffu, s, o);
        sq += __shfl_xor_sync(0xffffffffu, sq, o);
    }
    __shared__ float sa[8], sb[8];
    const int w = tid >> 5, l = tid & 31;
    if (l == 0) { sa[w] = s; sb[w] = sq; }
    __syncthreads();
    if (w == 0) {
        s  = (l < 8) ? sa[l] : 0.0f;
        sq = (l < 8) ? sb[l] : 0.0f;
#pragma unroll
        for (int o = 4; o > 0; o >>= 1) {
            s  += __shfl_xor_sync(0xffffffffu, s, o);
            sq += __shfl_xor_sync(0xffffffffu, sq, o);
        }
        if (l == 0) { sa[0] = s; sb[0] = sq; }
    }
    __syncthreads();
    const float mu  = sa[0] * (1.0f / DD);
    const float var = sb[0] * (1.0f / DD) - mu * mu;
    const float inv = rsqrtf(var + 1e-5f);
    const float4 gm = ((const float4*)gamma)[tid];
    const float4 bt = ((const float4*)lbeta)[tid];
    float4 o;
    o.x = (v.x - mu) * inv * gm.x + bt.x;
    o.y = (v.y - mu) * inv * gm.y + bt.y;
    o.z = (v.z - mu) * inv * gm.z + bt.z;
    o.w = (v.w - mu) * inv * gm.w + bt.w;
    ((float4*)(out + (size_t)row * DD))[tid] = o;
}

// ---------------- launch ----------------
extern "C" void kernel_launch(void* const* d_in, const int* in_sizes, int n_in,
                              void* d_out, int out_size)
{
    const float* x     = (const float*)d_in[0];
    const float* Wz    = (const float*)d_in[1];
    const float* bz    = (const float*)d_in[2];
    const float* Wh    = (const float*)d_in[3];
    const float* bh    = (const float*)d_in[4];
    const float* sbeta = (const float*)d_in[5];
    const float* gamma = (const float*)d_in[6];
    const float* lbeta = (const float*)d_in[7];
    float* out = (float*)d_out;

    convert_x_kernel<<<(MM * DD) / (256 * 4), 256>>>(x);
    transpose_kernel<<<dim3(32, 32, 2), 256>>>(Wz, Wh);

    dim3 gemmGrid(DD / 128, MM / 128);   // (8, 128)
    gemm_fused_kernel<<<gemmGrid, 256, SMEM_GEMM>>>(bz, bh);

    scan_pass1<<<(BB * NCHUNK * DD) / 256, 256>>>();
    scan_pass2<<<(BB * DD) / 256, 256>>>();
    scan_pass3<<<(BB * NCHUNK * DD) / 256, 256>>>(sbeta);

    ln_kernel<<<MM, 256>>>(out, gamma, lbeta);
}